// round 15
// baseline (speedup 1.0000x reference)
#include <cuda_runtime.h>
#include <cuda_bf16.h>
#include <cstdint>

// EdgePredictionHead: out[i,j] = node_emb[i,:].w_node + feature_emb[j,:].w_feat + b
//   node_emb:    [65536, 64] f32   (d_in[0])
//   feature_emb: [512, 64]   f32   (d_in[1])
//   W:           [1, 128]    f32   (d_in[2])  (w_node = W[0:64], w_feat = W[64:128])
//   b:           [1]         f32   (d_in[3])
//
// FINAL configuration — every choice below is measurement-backed (R2-R14):
//  - two-kernel: tiny feat projection + fused node_proj/broadcast streamer
//    (R7: fusing the 16MB node read into the 128MB store stream is free;
//     R11: per-block feat recompute is not — 262MB of L2 traffic)
//  - streamer: FLAT one-shot launch, 4 rows/warp, 16384 warps
//    (R11: persistent grid-stride collapses MLP/occupancy, 35.2us;
//     R12: RPW=8 halves warp count and regresses, 25.8us + tail)
//  - __stcs streaming stores
//    (R13: default write-back looks faster in isolation (24.8us) but defers
//     128MB of dirty-L2 writeback into the next graph replay, total 31us)
//  - PDL edge feat->streamer (R10: free, marginally best)
// Result: streamer at 5.94 TB/s = ~98% of the 6.06 TB/s measured store ceiling.

#define BS 65536
#define NF 512
#define D  64
#define ROWS_PER_WARP 4

// feat_proj + b scratch (allocation-free rule: __device__ global; 2KB, L2-resident).
__device__ float g_feat[NF];

// ---------------------------------------------------------------------------
// Kernel 1 (tiny): g_feat[j] = feature_emb[j,:] . W[64:128] + b
// warp-per-row, 512 rows -> 64 blocks x 256 threads.
// ---------------------------------------------------------------------------
__global__ __launch_bounds__(256) void feat_kernel(
    const float* __restrict__ feature_emb,
    const float* __restrict__ W,
    const float* __restrict__ b)
{
    const int warp = (blockIdx.x * 256 + threadIdx.x) >> 5;
    const int lane = threadIdx.x & 31;
    if (warp >= NF) return;

    const float2 v = reinterpret_cast<const float2*>(feature_emb)[warp * 32 + lane];
    const float2 w = reinterpret_cast<const float2*>(W)[32 + lane];  // W[64 + 2*lane ..]
    float p = fmaf(v.x, w.x, v.y * w.y);

    #pragma unroll
    for (int off = 16; off > 0; off >>= 1)
        p += __shfl_xor_sync(0xffffffffu, p, off);

    if (lane == 0)
        g_feat[warp] = p + b[0];
}

// ---------------------------------------------------------------------------
// Kernel 2: fused node_proj + broadcast stream (PDL). Warp handles 4 rows:
//   1. node-row loads + W load + dot/shfl  (independent of g_feat)
//   2. cudaGridDependencySynchronize()     (waits for feat_kernel grid)
//   3. g_feat loads + 16 independent STG.128 (.cs), 512 contiguous B/warp each
// ---------------------------------------------------------------------------
__global__ __launch_bounds__(256) void fused_stream_kernel(
    const float* __restrict__ node_emb,
    const float* __restrict__ W,
    float* __restrict__ out)
{
    const int warp = (blockIdx.x * 256 + threadIdx.x) >> 5;
    const int lane = threadIdx.x & 31;
    const int row0 = warp * ROWS_PER_WARP;

    // Front-batch all 4 node rows (fully coalesced float2 per lane).
    const float2* ne = reinterpret_cast<const float2*>(node_emb);
    const float2 v0 = ne[(row0 + 0) * 32 + lane];
    const float2 v1 = ne[(row0 + 1) * 32 + lane];
    const float2 v2 = ne[(row0 + 2) * 32 + lane];
    const float2 v3 = ne[(row0 + 3) * 32 + lane];
    const float2 w  = reinterpret_cast<const float2*>(W)[lane];   // w_node[2*lane..]

    // 4 independent butterfly reductions, interleaved per stage for ILP.
    float p[ROWS_PER_WARP];
    p[0] = fmaf(v0.x, w.x, v0.y * w.y);
    p[1] = fmaf(v1.x, w.x, v1.y * w.y);
    p[2] = fmaf(v2.x, w.x, v2.y * w.y);
    p[3] = fmaf(v3.x, w.x, v3.y * w.y);
    #pragma unroll
    for (int off = 16; off > 0; off >>= 1) {
        #pragma unroll
        for (int r = 0; r < ROWS_PER_WARP; r++)
            p[r] += __shfl_xor_sync(0xffffffffu, p[r], off);
    }

    // PDL: wait for feat_kernel's grid before touching g_feat.
    cudaGridDependencySynchronize();

    // Per-lane feat values, interleaved so each STG.128 covers 512B contiguous.
    const float4* f4 = reinterpret_cast<const float4*>(g_feat);
    const float4 f0 = f4[      lane];
    const float4 f1 = f4[ 32 + lane];
    const float4 f2 = f4[ 64 + lane];
    const float4 f3 = f4[ 96 + lane];

    float4* o4 = reinterpret_cast<float4*>(out + (size_t)row0 * NF);

    #pragma unroll
    for (int r = 0; r < ROWS_PER_WARP; r++) {
        const float pr = p[r];
        float4* row = o4 + r * (NF / 4);
        float4 t;
        t.x = f0.x + pr; t.y = f0.y + pr; t.z = f0.z + pr; t.w = f0.w + pr;
        __stcs(row +      lane, t);
        t.x = f1.x + pr; t.y = f1.y + pr; t.z = f1.z + pr; t.w = f1.w + pr;
        __stcs(row + 32 + lane, t);
        t.x = f2.x + pr; t.y = f2.y + pr; t.z = f2.z + pr; t.w = f2.w + pr;
        __stcs(row + 64 + lane, t);
        t.x = f3.x + pr; t.y = f3.y + pr; t.z = f3.z + pr; t.w = f3.w + pr;
        __stcs(row + 96 + lane, t);
    }
}

// ---------------------------------------------------------------------------
extern "C" void kernel_launch(void* const* d_in, const int* in_sizes, int n_in,
                              void* d_out, int out_size)
{
    const float* node_emb    = (const float*)d_in[0];
    const float* feature_emb = (const float*)d_in[1];
    const float* W           = (const float*)d_in[2];
    const float* b           = (const float*)d_in[3];
    float*       out         = (float*)d_out;

    // Kernel 1: 512 warps -> 64 blocks x 256 threads (~1.1us).
    feat_kernel<<<64, 256>>>(feature_emb, W, b);

    // Kernel 2 with programmatic dependent launch (graph-capturable edge).
    cudaLaunchConfig_t cfg = {};
    cfg.gridDim  = dim3(BS / (8 * ROWS_PER_WARP));   // 2048 blocks
    cfg.blockDim = dim3(256);
    cfg.stream   = 0;
    cudaLaunchAttribute attr[1];
    attr[0].id = cudaLaunchAttributeProgrammaticStreamSerialization;
    attr[0].val.programmaticStreamSerializationAllowed = 1;
    cfg.attrs    = attr;
    cfg.numAttrs = 1;
    cudaLaunchKernelEx(&cfg, fused_stream_kernel, node_emb, W, out);
}

// round 16
// speedup vs baseline: 1.0060x; 1.0060x over previous
#include <cuda_runtime.h>
#include <cuda_bf16.h>
#include <cstdint>

// EdgePredictionHead: out[i,j] = node_emb[i,:].w_node + feature_emb[j,:].w_feat + b
//   node_emb:    [65536, 64] f32   (d_in[0])
//   feature_emb: [512, 64]   f32   (d_in[1])
//   W:           [1, 128]    f32   (d_in[2])  (w_node = W[0:64], w_feat = W[64:128])
//   b:           [1]         f32   (d_in[3])
//
// Measurement-backed configuration (R2-R15):
//  - two-kernel: tiny feat projection + fused node_proj/broadcast streamer
//  - streamer: FLAT one-shot launch, 4 rows/warp, 16384 warps
//  - __stcs streaming stores (default write-back defers 128MB L2 writeback
//    into the next graph replay: R13)
//  - full PDL: PSS attribute on streamer + explicit
//    cudaTriggerProgrammaticLaunchCompletion in feat_kernel after the g_feat
//    store (this round's single-variable probe — lets the streamer launch
//    while feat_kernel blocks drain; writes before trigger are visible after
//    cudaGridDependencySynchronize per the PDL memory model).

#define BS 65536
#define NF 512
#define D  64
#define ROWS_PER_WARP 4

// feat_proj + b scratch (allocation-free rule: __device__ global; 2KB, L2-resident).
__device__ float g_feat[NF];

// ---------------------------------------------------------------------------
// Kernel 1 (tiny): g_feat[j] = feature_emb[j,:] . W[64:128] + b
// warp-per-row, 512 rows -> 64 blocks x 256 threads.
// ---------------------------------------------------------------------------
__global__ __launch_bounds__(256) void feat_kernel(
    const float* __restrict__ feature_emb,
    const float* __restrict__ W,
    const float* __restrict__ b)
{
    const int warp = (blockIdx.x * 256 + threadIdx.x) >> 5;
    const int lane = threadIdx.x & 31;

    if (warp < NF) {
        const float2 v = reinterpret_cast<const float2*>(feature_emb)[warp * 32 + lane];
        const float2 w = reinterpret_cast<const float2*>(W)[32 + lane];  // W[64 + 2*lane ..]
        float p = fmaf(v.x, w.x, v.y * w.y);

        #pragma unroll
        for (int off = 16; off > 0; off >>= 1)
            p += __shfl_xor_sync(0xffffffffu, p, off);

        if (lane == 0)
            g_feat[warp] = p + b[0];
    }

    // PDL primary-side trigger: g_feat writes for this block are done; allow
    // the dependent streamer grid to begin launching while we drain.
    cudaTriggerProgrammaticLaunchCompletion();
}

// ---------------------------------------------------------------------------
// Kernel 2: fused node_proj + broadcast stream (PDL). Warp handles 4 rows:
//   1. node-row loads + W load + dot/shfl  (independent of g_feat)
//   2. cudaGridDependencySynchronize()     (waits for feat_kernel triggers)
//   3. g_feat loads + 16 independent STG.128 (.cs), 512 contiguous B/warp each
// ---------------------------------------------------------------------------
__global__ __launch_bounds__(256) void fused_stream_kernel(
    const float* __restrict__ node_emb,
    const float* __restrict__ W,
    float* __restrict__ out)
{
    const int warp = (blockIdx.x * 256 + threadIdx.x) >> 5;
    const int lane = threadIdx.x & 31;
    const int row0 = warp * ROWS_PER_WARP;

    // Front-batch all 4 node rows (fully coalesced float2 per lane).
    const float2* ne = reinterpret_cast<const float2*>(node_emb);
    const float2 v0 = ne[(row0 + 0) * 32 + lane];
    const float2 v1 = ne[(row0 + 1) * 32 + lane];
    const float2 v2 = ne[(row0 + 2) * 32 + lane];
    const float2 v3 = ne[(row0 + 3) * 32 + lane];
    const float2 w  = reinterpret_cast<const float2*>(W)[lane];   // w_node[2*lane..]

    // 4 independent butterfly reductions, interleaved per stage for ILP.
    float p[ROWS_PER_WARP];
    p[0] = fmaf(v0.x, w.x, v0.y * w.y);
    p[1] = fmaf(v1.x, w.x, v1.y * w.y);
    p[2] = fmaf(v2.x, w.x, v2.y * w.y);
    p[3] = fmaf(v3.x, w.x, v3.y * w.y);
    #pragma unroll
    for (int off = 16; off > 0; off >>= 1) {
        #pragma unroll
        for (int r = 0; r < ROWS_PER_WARP; r++)
            p[r] += __shfl_xor_sync(0xffffffffu, p[r], off);
    }

    // PDL: wait for feat_kernel's triggers before touching g_feat.
    cudaGridDependencySynchronize();

    // Per-lane feat values, interleaved so each STG.128 covers 512B contiguous.
    const float4* f4 = reinterpret_cast<const float4*>(g_feat);
    const float4 f0 = f4[      lane];
    const float4 f1 = f4[ 32 + lane];
    const float4 f2 = f4[ 64 + lane];
    const float4 f3 = f4[ 96 + lane];

    float4* o4 = reinterpret_cast<float4*>(out + (size_t)row0 * NF);

    #pragma unroll
    for (int r = 0; r < ROWS_PER_WARP; r++) {
        const float pr = p[r];
        float4* row = o4 + r * (NF / 4);
        float4 t;
        t.x = f0.x + pr; t.y = f0.y + pr; t.z = f0.z + pr; t.w = f0.w + pr;
        __stcs(row +      lane, t);
        t.x = f1.x + pr; t.y = f1.y + pr; t.z = f1.z + pr; t.w = f1.w + pr;
        __stcs(row + 32 + lane, t);
        t.x = f2.x + pr; t.y = f2.y + pr; t.z = f2.z + pr; t.w = f2.w + pr;
        __stcs(row + 64 + lane, t);
        t.x = f3.x + pr; t.y = f3.y + pr; t.z = f3.z + pr; t.w = f3.w + pr;
        __stcs(row + 96 + lane, t);
    }
}

// ---------------------------------------------------------------------------
extern "C" void kernel_launch(void* const* d_in, const int* in_sizes, int n_in,
                              void* d_out, int out_size)
{
    const float* node_emb    = (const float*)d_in[0];
    const float* feature_emb = (const float*)d_in[1];
    const float* W           = (const float*)d_in[2];
    const float* b           = (const float*)d_in[3];
    float*       out         = (float*)d_out;

    // Kernel 1: 512 warps -> 64 blocks x 256 threads (~1.1us).
    feat_kernel<<<64, 256>>>(feature_emb, W, b);

    // Kernel 2 with programmatic dependent launch (graph-capturable edge).
    cudaLaunchConfig_t cfg = {};
    cfg.gridDim  = dim3(BS / (8 * ROWS_PER_WARP));   // 2048 blocks
    cfg.blockDim = dim3(256);
    cfg.stream   = 0;
    cudaLaunchAttribute attr[1];
    attr[0].id = cudaLaunchAttributeProgrammaticStreamSerialization;
    attr[0].val.programmaticStreamSerializationAllowed = 1;
    cfg.attrs    = attr;
    cfg.numAttrs = 1;
    cudaLaunchKernelEx(&cfg, fused_stream_kernel, node_emb, W, out);
}